// round 4
// baseline (speedup 1.0000x reference)
#include <cuda_runtime.h>
#include <cstdint>

// RobustTripletLoss — N=4096, D=512, C=128, TOPK=12
// K0: row norms
// K1: symmetric fp32 GEMM, fma.rn.f32x2 with pre-duplicated A smem (no packs in
//     inner loop) -> 64MB dist scratch
// K2: per-row reduce — register-resident top-12, partitionable-threefry gumbel
// K3: deterministic final reduce -> out[0]=loss, out[1]=(float)correct

namespace {

constexpr int NROW = 4096;
constexpr int DIM  = 512;
constexpr int NCLS = 128;
constexpr int KTOP = 12;

__device__ float g_dist[(size_t)NROW * NROW];
__device__ float g_sq[NROW];
__device__ float g_rowloss[NROW];
__device__ int   g_flags[NROW];

// ---------------- threefry2x32-20 (exact JAX semantics) ----------------
__host__ __device__ inline uint2 tf2x32(unsigned k0, unsigned k1,
                                        unsigned x0, unsigned x1) {
    unsigned ks2 = k0 ^ k1 ^ 0x1BD11BDAu;
    x0 += k0; x1 += k1;
#define TF_R(r) { x0 += x1; x1 = (x1 << (r)) | (x1 >> (32 - (r))); x1 ^= x0; }
    TF_R(13) TF_R(15) TF_R(26) TF_R(6)
    x0 += k1;  x1 += ks2 + 1u;
    TF_R(17) TF_R(29) TF_R(16) TF_R(24)
    x0 += ks2; x1 += k0 + 2u;
    TF_R(13) TF_R(15) TF_R(26) TF_R(6)
    x0 += k0;  x1 += k1 + 3u;
    TF_R(17) TF_R(29) TF_R(16) TF_R(24)
    x0 += k1;  x1 += ks2 + 4u;
    TF_R(13) TF_R(15) TF_R(26) TF_R(6)
    x0 += ks2; x1 += k0 + 5u;
#undef TF_R
    uint2 r; r.x = x0; r.y = x1; return r;
}

// partitionable random_bits (32-bit draws), linear index m
__device__ __forceinline__ unsigned rbits32(unsigned k0, unsigned k1, unsigned m) {
    uint2 e = tf2x32(k0, k1, 0u, m);
    return e.x ^ e.y;
}

// ---------------- packed f32x2 helpers ----------------
__device__ __forceinline__ void unpack2(unsigned long long v, float& lo, float& hi) {
    asm("mov.b64 {%0, %1}, %2;" : "=f"(lo), "=f"(hi) : "l"(v));
}
__device__ __forceinline__ void fma2(unsigned long long& d,
                                     unsigned long long a, unsigned long long b) {
    asm("fma.rn.f32x2 %0, %1, %2, %0;" : "+l"(d) : "l"(a), "l"(b));
}

__device__ __forceinline__ float devInf() { return __int_as_float(0x7f800000); }

// ---------------- K0: row squared norms ----------------
__global__ void __launch_bounds__(256) k_sq(const float* __restrict__ X) {
    int row  = blockIdx.x * 8 + (threadIdx.x >> 5);
    int lane = threadIdx.x & 31;
    const float* p = X + (size_t)row * DIM;
    float s = 0.f;
#pragma unroll
    for (int k = lane; k < DIM; k += 32) { float v = p[k]; s = fmaf(v, v, s); }
#pragma unroll
    for (int o = 16; o > 0; o >>= 1) s += __shfl_xor_sync(0xffffffffu, s, o);
    if (lane == 0) g_sq[row] = s;
}

// ---------------- K1: symmetric GEMM + dist epilogue ----------------
// 128x128 tile, BK=16, 256 threads, 8x8 per thread.
// A stored duplicated (v,v) so FFMA2 operands load straight from smem.
// Accumulators pair adjacent N columns.
__global__ void __launch_bounds__(256) k_gemm(const float* __restrict__ X) {
    const int bi = blockIdx.y, bj = blockIdx.x;
    if (bj < bi) return;

    __shared__ __align__(16) float AsD[16][256];  // duplicated pairs
    __shared__ __align__(16) float Bs[16][128];

    const int tid = threadIdx.x;
    const int tx = tid & 15, ty = tid >> 4;
    const int rm = ty * 8, rn = tx * 8;
    const int lrow = tid >> 1;
    const int lcol = (tid & 1) * 8;

    const float* Ap = X + (size_t)(bi * 128 + lrow) * DIM + lcol;
    const float* Bp = X + (size_t)(bj * 128 + lrow) * DIM + lcol;

    unsigned long long acc[8][4];  // [m][n-pair]
#pragma unroll
    for (int a = 0; a < 8; a++)
#pragma unroll
        for (int b = 0; b < 4; b++) acc[a][b] = 0ull;

    for (int k0 = 0; k0 < DIM; k0 += 16) {
        float4 a0 = *(const float4*)(Ap + k0);
        float4 a1 = *(const float4*)(Ap + k0 + 4);
        float4 b0 = *(const float4*)(Bp + k0);
        float4 b1 = *(const float4*)(Bp + k0 + 4);
        __syncthreads();
        float av8[8] = {a0.x, a0.y, a0.z, a0.w, a1.x, a1.y, a1.z, a1.w};
        float bv8[8] = {b0.x, b0.y, b0.z, b0.w, b1.x, b1.y, b1.z, b1.w};
#pragma unroll
        for (int c = 0; c < 8; c++) {
            float2 dpair; dpair.x = av8[c]; dpair.y = av8[c];
            *(float2*)&AsD[lcol + c][2 * lrow] = dpair;
            Bs[lcol + c][lrow] = bv8[c];
        }
        __syncthreads();
#pragma unroll
        for (int k = 0; k < 16; k++) {
            ulonglong2 A0 = *(const ulonglong2*)&AsD[k][2 * rm];
            ulonglong2 A1 = *(const ulonglong2*)&AsD[k][2 * rm + 4];
            ulonglong2 A2 = *(const ulonglong2*)&AsD[k][2 * rm + 8];
            ulonglong2 A3 = *(const ulonglong2*)&AsD[k][2 * rm + 12];
            ulonglong2 B0 = *(const ulonglong2*)&Bs[k][rn];
            ulonglong2 B1 = *(const ulonglong2*)&Bs[k][rn + 4];
            unsigned long long av[8] = {A0.x, A0.y, A1.x, A1.y,
                                        A2.x, A2.y, A3.x, A3.y};
            unsigned long long bv[4] = {B0.x, B0.y, B1.x, B1.y};
#pragma unroll
            for (int a = 0; a < 8; a++)
#pragma unroll
                for (int b = 0; b < 4; b++) fma2(acc[a][b], av[a], bv[b]);
        }
    }

    float sqm[8], sqn[8];
#pragma unroll
    for (int a = 0; a < 8; a++) sqm[a] = g_sq[bi * 128 + rm + a];
#pragma unroll
    for (int b = 0; b < 8; b++) sqn[b] = g_sq[bj * 128 + rn + b];

#pragma unroll
    for (int a = 0; a < 8; a++) {
        int gi = bi * 128 + rm + a;
#pragma unroll
        for (int b = 0; b < 4; b++) {
            float lo, hi; unpack2(acc[a][b], lo, hi);
            int gj0 = bj * 128 + rn + 2 * b;
            float d0 = sqrtf(fmaxf(sqm[a] + sqn[2 * b]     - 2.f * lo, 1e-12f));
            float d1 = sqrtf(fmaxf(sqm[a] + sqn[2 * b + 1] - 2.f * hi, 1e-12f));
            g_dist[(size_t)gi * NROW + gj0]     = d0;
            g_dist[(size_t)gi * NROW + gj0 + 1] = d1;
            if (bi != bj) {
                g_dist[(size_t)gj0 * NROW + gi]       = d0;
                g_dist[(size_t)(gj0 + 1) * NROW + gi] = d1;
            }
        }
    }
}

// ---------------- block-wide u64 max reduce (broadcast result) ----------------
__device__ unsigned long long blockMax64(unsigned long long v,
                                         volatile unsigned long long* sh, int tid) {
#pragma unroll
    for (int o = 16; o > 0; o >>= 1) {
        unsigned long long o2 = __shfl_xor_sync(0xffffffffu, v, o);
        if (o2 > v) v = o2;
    }
    if ((tid & 31) == 0) sh[tid >> 5] = v;
    __syncthreads();
    if (tid == 0) {
        unsigned long long m = sh[0];
#pragma unroll
        for (int w = 1; w < 8; w++) { unsigned long long x = sh[w]; if (x > m) m = x; }
        sh[8] = m;
    }
    __syncthreads();
    return sh[8];
}

// ---------------- K2: per-row reduce ----------------
__global__ void __launch_bounds__(256) k_row(
    const float* __restrict__ pred, const int* __restrict__ targets,
    const float* __restrict__ prob, const float* __restrict__ thrp,
    unsigned kp0, unsigned kp1, unsigned q0, unsigned q1)
{
    const int i = blockIdx.x;
    const int tid = threadIdx.x;
    const float thr = *thrp;
    const int ti = targets[i];
    const float* grow = g_dist + (size_t)i * NROW;
    const float INF = devInf();

    __shared__ unsigned long long sh[9];

    // fill pass: register-resident neg-masked dists, local top candidate,
    // gumbel candidates (threefry only at same-class positions)
    float lv[16];
    unsigned long long g1 = 0, g2 = 0, cand = 0;
    const unsigned mrow = (unsigned)i * (unsigned)NROW;
#pragma unroll
    for (int w = 0; w < 16; w++) {
        int j = tid + w * 256;
        float d = grow[j];
        bool same = (targets[j] == ti);
        float v = same ? INF : d;
        lv[w] = v;
        unsigned fb = __float_as_uint(v);
        unsigned long long sc = ~(((unsigned long long)fb << 13) | (unsigned)j);
        if (sc > cand) cand = sc;
        if (same && j != i) {
            unsigned m = mrow + (unsigned)j;
            unsigned b1 = rbits32(kp0, kp1, m);
            unsigned long long s1 = (1ULL << 62) |
                ((unsigned long long)(b1 >> 9) << 13) | (unsigned)(NROW - 1 - j);
            if (s1 > g1) g1 = s1;
            if (prob[j] >= thr) {
                unsigned b2 = rbits32(q0, q1, m);
                unsigned long long s2 = (1ULL << 62) |
                    ((unsigned long long)(b2 >> 9) << 13) | (unsigned)(NROW - 1 - j);
                if (s2 > g2) g2 = s2;
            }
        }
    }

    unsigned long long r1 = blockMax64(g1, sh, tid);
    unsigned long long r2 = blockMax64(g2, sh, tid);
    int ap_idx  = r1 ? (NROW - 1 - (int)(r1 & 0x1FFFu)) : 0;
    int new_pos = r2 ? (NROW - 1 - (int)(r2 & 0x1FFFu)) : ap_idx;

    // stable top-12: 12 rounds of block argmin over per-thread candidates;
    // only the owner thread rescans its 16 register values.
    int st[KTOP];
#pragma unroll
    for (int t = 0; t < KTOP; t++) {
        unsigned long long r = blockMax64(cand, sh, tid);
        int sel = (int)((~r) & 0x1FFFu);
        st[t] = sel;                         // uniform across threads
        if ((sel & 255) == tid) {
            lv[sel >> 8] = INF;
            unsigned long long c2 = 0;
#pragma unroll
            for (int w = 0; w < 16; w++) {
                unsigned fb = __float_as_uint(lv[w]);
                unsigned long long sc = ~(((unsigned long long)fb << 13) |
                                          (unsigned)(tid + w * 256));
                if (sc > c2) c2 = sc;
            }
            cand = c2;
        }
    }
    int an_idx = st[0];

    // argmax over prediction[an_idx] (first occurrence on ties)
    unsigned long long pm = 0;
    if (tid < NCLS) {
        float v = pred[(size_t)an_idx * NCLS + tid];
        unsigned b = __float_as_uint(v);
        unsigned ord = (b & 0x80000000u) ? ~b : (b | 0x80000000u);
        pm = ((unsigned long long)ord << 13) | (unsigned)(NCLS - 1 - tid);
    }
    unsigned long long rp = blockMax64(pm, sh, tid);
    int pargmax = NCLS - 1 - (int)(rp & 0x1FFFu);

    if (tid == 0) {
        float ap0 = grow[ap_idx];
        float an0 = grow[an_idx];
        bool pos_conf = prob[ap_idx] >= thr;
        bool neg_conf = prob[an_idx] >= thr;
        bool is_fn = (pargmax == ti);

        int rsel = KTOP - 1;
#pragma unroll
        for (int t = KTOP - 2; t >= 1; t--) {
            if (prob[st[t]] >= thr) rsel = t;
        }
        float an_B   = grow[st[rsel]];
        float ap_new = grow[new_pos];

        bool caseB   = pos_conf && !neg_conf && is_fn;
        bool swapc   = !pos_conf && (neg_conf || !is_fn);
        bool inverse = !pos_conf && !neg_conf && is_fn;
        float half = (ap0 + an0) * 0.5f;
        float ap = caseB ? half : (swapc ? ap_new : ap0);
        float an = caseB ? an_B : (swapc ? half  : an0);
        float rl = inverse ? fmaxf(an - ap + 0.3f, 0.f)
                           : fmaxf(ap - an + 0.3f, 0.f);
        bool conf = prob[i] >= thr;
        g_rowloss[i] = conf ? rl : 0.f;
        g_flags[i] = (conf ? 1 : 0) | ((conf && an >= ap) ? 2 : 0);
    }
}

// ---------------- K3: deterministic final reduce ----------------
__global__ void __launch_bounds__(256) k_final(float* out) {
    __shared__ float ss[256];
    __shared__ int sc[256], sk[256];
    int tid = threadIdx.x;
    float s = 0.f; int c = 0, k = 0;
    for (int r = tid; r < NROW; r += 256) {
        s += g_rowloss[r];
        int f = g_flags[r];
        c += f & 1;
        k += (f >> 1) & 1;
    }
    ss[tid] = s; sc[tid] = c; sk[tid] = k;
    __syncthreads();
    for (int o = 128; o > 0; o >>= 1) {
        if (tid < o) { ss[tid] += ss[tid + o]; sc[tid] += sc[tid + o]; sk[tid] += sk[tid + o]; }
        __syncthreads();
    }
    if (tid == 0) {
        int cnt = sc[0]; if (cnt < 1) cnt = 1;
        out[0] = ss[0] / (float)cnt;
        out[1] = (float)sk[0];
    }
}

}  // namespace

extern "C" void kernel_launch(void* const* d_in, const int* in_sizes, int n_in,
                              void* d_out, int out_size) {
    const float* X       = (const float*)d_in[0];
    const float* pred    = (const float*)d_in[1];
    const int*   targets = (const int*)d_in[2];
    // d_in[3] = true_targets (unused by reference)
    const float* prob    = (const float*)d_in[4];
    const float* thr     = (const float*)d_in[5];
    float* out = (float*)d_out;

    // JAX partitionable split: child key i = threefry2x32((0,42), (0, i))
    uint2 kp  = tf2x32(0u, 42u, 0u, 0u);
    uint2 kp2 = tf2x32(0u, 42u, 0u, 1u);

    k_sq<<<NROW / 8, 256>>>(X);
    dim3 g(NROW / 128, NROW / 128);
    k_gemm<<<g, 256>>>(X);
    k_row<<<NROW, 256>>>(pred, targets, prob, thr, kp.x, kp.y, kp2.x, kp2.y);
    k_final<<<1, 256>>>(out);
}

// round 6
// speedup vs baseline: 1.9606x; 1.9606x over previous
#include <cuda_runtime.h>
#include <cuda_bf16.h>
#include <cstdint>

// RobustTripletLoss — N=4096, D=512, C=128, TOPK=12
// k_prep : X fp32 -> (Xhi, Xlo) bf16 split + row sq-norms
// k_gemm : HMMA (mma.sync bf16) symmetric Gram, 3-term hi/lo split, cp.async
//          double-buffered -> dist (64MB scratch)
// k_row  : per-row reduce (top-12, partitionable-threefry gumbel, case logic)
// k_final: deterministic reduce -> out[0]=loss, out[1]=(float)correct

namespace {

constexpr int NROW = 4096;
constexpr int DIM  = 512;
constexpr int NCLS = 128;
constexpr int KTOP = 12;

__device__ __align__(16) float g_dist[(size_t)NROW * NROW];
__device__ __align__(16) float g_sq[NROW];
__device__ __align__(16) __nv_bfloat16 g_xhi[(size_t)NROW * DIM];
__device__ __align__(16) __nv_bfloat16 g_xlo[(size_t)NROW * DIM];
__device__ float g_rowloss[NROW];
__device__ int   g_flags[NROW];

// ---------------- threefry2x32-20 (exact JAX semantics) ----------------
__host__ __device__ inline uint2 tf2x32(unsigned k0, unsigned k1,
                                        unsigned x0, unsigned x1) {
    unsigned ks2 = k0 ^ k1 ^ 0x1BD11BDAu;
    x0 += k0; x1 += k1;
#define TF_R(r) { x0 += x1; x1 = (x1 << (r)) | (x1 >> (32 - (r))); x1 ^= x0; }
    TF_R(13) TF_R(15) TF_R(26) TF_R(6)
    x0 += k1;  x1 += ks2 + 1u;
    TF_R(17) TF_R(29) TF_R(16) TF_R(24)
    x0 += ks2; x1 += k0 + 2u;
    TF_R(13) TF_R(15) TF_R(26) TF_R(6)
    x0 += k0;  x1 += k1 + 3u;
    TF_R(17) TF_R(29) TF_R(16) TF_R(24)
    x0 += k1;  x1 += ks2 + 4u;
    TF_R(13) TF_R(15) TF_R(26) TF_R(6)
    x0 += ks2; x1 += k0 + 5u;
#undef TF_R
    uint2 r; r.x = x0; r.y = x1; return r;
}

__device__ __forceinline__ unsigned rbits32(unsigned k0, unsigned k1, unsigned m) {
    uint2 e = tf2x32(k0, k1, 0u, m);
    return e.x ^ e.y;
}

__device__ __forceinline__ float devInf() { return __int_as_float(0x7f800000); }

__device__ __forceinline__ uint32_t smem_to_u32(const void* p) {
    uint32_t a;
    asm("{ .reg .u64 t; cvta.to.shared.u64 t, %1; cvt.u32.u64 %0, t; }"
        : "=r"(a) : "l"(p));
    return a;
}

// ---------------- k_prep: bf16 hi/lo split + row norms ----------------
__global__ void __launch_bounds__(256) k_prep(const float* __restrict__ X) {
    int row  = blockIdx.x * 8 + (threadIdx.x >> 5);
    int lane = threadIdx.x & 31;
    const float4* p = (const float4*)(X + (size_t)row * DIM);
    float s = 0.f;
#pragma unroll
    for (int it = 0; it < 4; it++) {
        int f = lane + it * 32;
        float4 v = p[f];
        s = fmaf(v.x, v.x, fmaf(v.y, v.y, fmaf(v.z, v.z, fmaf(v.w, v.w, s))));
        __nv_bfloat16 h0 = __float2bfloat16(v.x);
        __nv_bfloat16 h1 = __float2bfloat16(v.y);
        __nv_bfloat16 h2 = __float2bfloat16(v.z);
        __nv_bfloat16 h3 = __float2bfloat16(v.w);
        __nv_bfloat16 l0 = __float2bfloat16(v.x - __bfloat162float(h0));
        __nv_bfloat16 l1 = __float2bfloat16(v.y - __bfloat162float(h1));
        __nv_bfloat16 l2 = __float2bfloat16(v.z - __bfloat162float(h2));
        __nv_bfloat16 l3 = __float2bfloat16(v.w - __bfloat162float(h3));
        size_t base = (size_t)row * DIM + (size_t)f * 4;
        *(__nv_bfloat162*)&g_xhi[base]     = __halves2bfloat162(h0, h1);
        *(__nv_bfloat162*)&g_xhi[base + 2] = __halves2bfloat162(h2, h3);
        *(__nv_bfloat162*)&g_xlo[base]     = __halves2bfloat162(l0, l1);
        *(__nv_bfloat162*)&g_xlo[base + 2] = __halves2bfloat162(l2, l3);
    }
#pragma unroll
    for (int o = 16; o > 0; o >>= 1) s += __shfl_xor_sync(0xffffffffu, s, o);
    if (lane == 0) g_sq[row] = s;
}

// ---------------- k_gemm: HMMA bf16x3 symmetric Gram ----------------
// smem layout (dynamic):
//   [0..512)    sqn staging (float[128])
//   [512..)     two 32KB buffers, each = A tile 16KB + B tile 16KB
//   Dt (float 128x129 = 66048B) reuses [512..66560) after compute
constexpr int OFF_BUF  = 512;
constexpr int BUF_SZ   = 32768;      // A 16K + B 16K
constexpr int SMEM_DYN = 512 + 128 * 129 * 4;  // 66560 (> 512 + 2*32768 = 66048)

// tile rows: 128 rows x 64 bf16 (= 128B). swizzle: 16B group g at row r stored
// at group (g ^ (r & 7)).
__device__ __forceinline__ void prefetch_chunk(
    const __nv_bfloat16* __restrict__ srcA, const __nv_bfloat16* __restrict__ srcB,
    int bi, int bj, int kb, uint32_t sbuf, int tid)
{
#pragma unroll
    for (int it = 0; it < 4; it++) {
        int idx = tid + it * 256;
        int row = idx >> 3, g = idx & 7;
        unsigned sw = ((unsigned)(g ^ (row & 7))) << 4;
        const void* gA = srcA + (size_t)(bi * 128 + row) * DIM + kb * 64 + g * 8;
        uint32_t dA = sbuf + row * 128 + sw;
        asm volatile("cp.async.cg.shared.global [%0], [%1], 16;" :: "r"(dA), "l"(gA));
        const void* gB = srcB + (size_t)(bj * 128 + row) * DIM + kb * 64 + g * 8;
        uint32_t dB = sbuf + 16384 + row * 128 + sw;
        asm volatile("cp.async.cg.shared.global [%0], [%1], 16;" :: "r"(dB), "l"(gB));
    }
    asm volatile("cp.async.commit_group;" ::: "memory");
}

__device__ __forceinline__ void mma16816(float* c, const uint32_t* a,
                                         const uint32_t* b) {
    asm volatile(
        "mma.sync.aligned.m16n8k16.row.col.f32.bf16.bf16.f32 "
        "{%0,%1,%2,%3}, {%4,%5,%6,%7}, {%8,%9}, {%0,%1,%2,%3};"
        : "+f"(c[0]), "+f"(c[1]), "+f"(c[2]), "+f"(c[3])
        : "r"(a[0]), "r"(a[1]), "r"(a[2]), "r"(a[3]), "r"(b[0]), "r"(b[1]));
}

__global__ void __launch_bounds__(256) k_gemm() {
    const int bi = blockIdx.y, bj = blockIdx.x;
    if (bj < bi) return;

    extern __shared__ __align__(16) char smem[];
    const uint32_t sb = smem_to_u32(smem);
    const int tid = threadIdx.x;
    const int wid = tid >> 5, lane = tid & 31;
    const int wm = wid & 1, wn = wid >> 1;     // 2 x 4 warp grid, warp tile 64x32

    if (tid < 128) ((float*)smem)[tid] = g_sq[bj * 128 + tid];

    float acc[4][4][4] = {};

    // chunk c (0..23): term t = c>>3 in {(hi,hi),(hi,lo),(lo,hi)}, kb = c&7
    prefetch_chunk(g_xhi, g_xhi, bi, bj, 0, sb + OFF_BUF, tid);

#pragma unroll 1
    for (int c = 0; c < 24; c++) {
        if (c + 1 < 24) {
            int t = (c + 1) >> 3, kb = (c + 1) & 7;
            const __nv_bfloat16* sA = (t < 2) ? g_xhi : g_xlo;
            const __nv_bfloat16* sB = (t == 1) ? g_xlo : g_xhi;
            prefetch_chunk(sA, sB, bi, bj, kb, sb + OFF_BUF + ((c + 1) & 1) * BUF_SZ, tid);
            asm volatile("cp.async.wait_group %0;" :: "n"(1) : "memory");
        } else {
            asm volatile("cp.async.wait_group %0;" :: "n"(0) : "memory");
        }
        __syncthreads();

        const uint32_t sA = sb + OFF_BUF + (c & 1) * BUF_SZ;
        const uint32_t sB = sA + 16384;
#pragma unroll
        for (int ks = 0; ks < 4; ks++) {
            uint32_t a[4][4], b[4][2];
#pragma unroll
            for (int mf = 0; mf < 4; mf++) {
                int row = wm * 64 + mf * 16 + (lane & 15);
                int kg = ks * 2 + (lane >> 4);
                uint32_t addr = sA + row * 128 + (((unsigned)(kg ^ (row & 7))) << 4);
                asm volatile(
                    "ldmatrix.sync.aligned.m8n8.x4.shared.b16 {%0,%1,%2,%3}, [%4];"
                    : "=r"(a[mf][0]), "=r"(a[mf][1]), "=r"(a[mf][2]), "=r"(a[mf][3])
                    : "r"(addr));
            }
#pragma unroll
            for (int nf = 0; nf < 4; nf++) {
                int row = wn * 32 + nf * 8 + (lane & 7);
                int kg = ks * 2 + ((lane >> 3) & 1);
                uint32_t addr = sB + row * 128 + (((unsigned)(kg ^ (row & 7))) << 4);
                asm volatile(
                    "ldmatrix.sync.aligned.m8n8.x2.shared.b16 {%0,%1}, [%2];"
                    : "=r"(b[nf][0]), "=r"(b[nf][1]) : "r"(addr));
            }
#pragma unroll
            for (int mf = 0; mf < 4; mf++)
#pragma unroll
                for (int nf = 0; nf < 4; nf++)
                    mma16816(acc[mf][nf], a[mf], b[nf]);
        }
        __syncthreads();
    }

    // ---------- epilogue: dist -> smem tile -> coalesced (+mirror) stores ----
    const float* s_sqn = (const float*)smem;
    float* Dt = (float*)(smem + OFF_BUF);
    const int gq = lane >> 2, tl = lane & 3;

#pragma unroll
    for (int mf = 0; mf < 4; mf++) {
#pragma unroll
        for (int q = 0; q < 2; q++) {
            int m = wm * 64 + mf * 16 + q * 8 + gq;
            float sqm = g_sq[bi * 128 + m];
#pragma unroll
            for (int nf = 0; nf < 4; nf++) {
                int n = wn * 32 + nf * 8 + tl * 2;
                float v0 = acc[mf][nf][q * 2 + 0];
                float v1 = acc[mf][nf][q * 2 + 1];
                float d0 = sqrtf(fmaxf(sqm + s_sqn[n]     - 2.f * v0, 1e-12f));
                float d1 = sqrtf(fmaxf(sqm + s_sqn[n + 1] - 2.f * v1, 1e-12f));
                Dt[m * 129 + n]     = d0;
                Dt[m * 129 + n + 1] = d1;
            }
        }
    }
    __syncthreads();

#pragma unroll
    for (int k = 0; k < 16; k++) {
        int idx = tid + k * 256;
        int row = idx >> 5, c4 = idx & 31;
        float4 v;
        v.x = Dt[row * 129 + c4 * 4 + 0];
        v.y = Dt[row * 129 + c4 * 4 + 1];
        v.z = Dt[row * 129 + c4 * 4 + 2];
        v.w = Dt[row * 129 + c4 * 4 + 3];
        *(float4*)&g_dist[(size_t)(bi * 128 + row) * NROW + bj * 128 + c4 * 4] = v;
    }
    if (bi != bj) {
#pragma unroll
        for (int k = 0; k < 16; k++) {
            int idx = tid + k * 256;
            int mrow = idx >> 5, c4 = idx & 31;
            float4 v;
            v.x = Dt[(c4 * 4 + 0) * 129 + mrow];
            v.y = Dt[(c4 * 4 + 1) * 129 + mrow];
            v.z = Dt[(c4 * 4 + 2) * 129 + mrow];
            v.w = Dt[(c4 * 4 + 3) * 129 + mrow];
            *(float4*)&g_dist[(size_t)(bj * 128 + mrow) * NROW + bi * 128 + c4 * 4] = v;
        }
    }
}

// ---------------- block-wide u64 max reduce (broadcast result) ----------------
__device__ unsigned long long blockMax64(unsigned long long v,
                                         volatile unsigned long long* sh, int tid) {
#pragma unroll
    for (int o = 16; o > 0; o >>= 1) {
        unsigned long long o2 = __shfl_xor_sync(0xffffffffu, v, o);
        if (o2 > v) v = o2;
    }
    if ((tid & 31) == 0) sh[tid >> 5] = v;
    __syncthreads();
    if (tid == 0) {
        unsigned long long m = sh[0];
#pragma unroll
        for (int w = 1; w < 8; w++) { unsigned long long x = sh[w]; if (x > m) m = x; }
        sh[8] = m;
    }
    __syncthreads();
    return sh[8];
}

// ---------------- k_row: per-row reduce ----------------
__global__ void __launch_bounds__(256) k_row(
    const float* __restrict__ pred, const int* __restrict__ targets,
    const float* __restrict__ prob, const float* __restrict__ thrp,
    unsigned kp0, unsigned kp1, unsigned q0, unsigned q1)
{
    const int i = blockIdx.x;
    const int tid = threadIdx.x;
    const float thr = *thrp;
    const int ti = targets[i];
    const float* grow = g_dist + (size_t)i * NROW;
    const float INF = devInf();

    __shared__ unsigned long long sh[9];

    float lv[16];
    unsigned long long g1 = 0, g2 = 0, cand = 0;
    const unsigned mrow = (unsigned)i * (unsigned)NROW;
#pragma unroll
    for (int w = 0; w < 16; w++) {
        int j = tid + w * 256;
        float d = grow[j];
        bool same = (targets[j] == ti);
        float v = same ? INF : d;
        lv[w] = v;
        unsigned fb = __float_as_uint(v);
        unsigned long long sc = ~(((unsigned long long)fb << 13) | (unsigned)j);
        if (sc > cand) cand = sc;
        if (same && j != i) {
            unsigned m = mrow + (unsigned)j;
            unsigned b1 = rbits32(kp0, kp1, m);
            unsigned long long s1 = (1ULL << 62) |
                ((unsigned long long)(b1 >> 9) << 13) | (unsigned)(NROW - 1 - j);
            if (s1 > g1) g1 = s1;
            if (prob[j] >= thr) {
                unsigned b2 = rbits32(q0, q1, m);
                unsigned long long s2 = (1ULL << 62) |
                    ((unsigned long long)(b2 >> 9) << 13) | (unsigned)(NROW - 1 - j);
                if (s2 > g2) g2 = s2;
            }
        }
    }

    unsigned long long r1 = blockMax64(g1, sh, tid);
    unsigned long long r2 = blockMax64(g2, sh, tid);
    int ap_idx  = r1 ? (NROW - 1 - (int)(r1 & 0x1FFFu)) : 0;
    int new_pos = r2 ? (NROW - 1 - (int)(r2 & 0x1FFFu)) : ap_idx;

    int st[KTOP];
#pragma unroll
    for (int t = 0; t < KTOP; t++) {
        unsigned long long r = blockMax64(cand, sh, tid);
        int sel = (int)((~r) & 0x1FFFu);
        st[t] = sel;
        if ((sel & 255) == tid) {
            lv[sel >> 8] = INF;
            unsigned long long c2 = 0;
#pragma unroll
            for (int w = 0; w < 16; w++) {
                unsigned fb = __float_as_uint(lv[w]);
                unsigned long long sc = ~(((unsigned long long)fb << 13) |
                                          (unsigned)(tid + w * 256));
                if (sc > c2) c2 = sc;
            }
            cand = c2;
        }
    }
    int an_idx = st[0];

    unsigned long long pm = 0;
    if (tid < NCLS) {
        float v = pred[(size_t)an_idx * NCLS + tid];
        unsigned b = __float_as_uint(v);
        unsigned ord = (b & 0x80000000u) ? ~b : (b | 0x80000000u);
        pm = ((unsigned long long)ord << 13) | (unsigned)(NCLS - 1 - tid);
    }
    unsigned long long rp = blockMax64(pm, sh, tid);
    int pargmax = NCLS - 1 - (int)(rp & 0x1FFFu);

    if (tid == 0) {
        float ap0 = grow[ap_idx];
        float an0 = grow[an_idx];
        bool pos_conf = prob[ap_idx] >= thr;
        bool neg_conf = prob[an_idx] >= thr;
        bool is_fn = (pargmax == ti);

        int rsel = KTOP - 1;
#pragma unroll
        for (int t = KTOP - 2; t >= 1; t--) {
            if (prob[st[t]] >= thr) rsel = t;
        }
        float an_B   = grow[st[rsel]];
        float ap_new = grow[new_pos];

        bool caseB   = pos_conf && !neg_conf && is_fn;
        bool swapc   = !pos_conf && (neg_conf || !is_fn);
        bool inverse = !pos_conf && !neg_conf && is_fn;
        float half = (ap0 + an0) * 0.5f;
        float ap = caseB ? half : (swapc ? ap_new : ap0);
        float an = caseB ? an_B : (swapc ? half  : an0);
        float rl = inverse ? fmaxf(an - ap + 0.3f, 0.f)
                           : fmaxf(ap - an + 0.3f, 0.f);
        bool conf = prob[i] >= thr;
        g_rowloss[i] = conf ? rl : 0.f;
        g_flags[i] = (conf ? 1 : 0) | ((conf && an >= ap) ? 2 : 0);
    }
}

// ---------------- k_final: deterministic final reduce ----------------
__global__ void __launch_bounds__(256) k_final(float* out) {
    __shared__ float ss[256];
    __shared__ int sc[256], sk[256];
    int tid = threadIdx.x;
    float s = 0.f; int c = 0, k = 0;
    for (int r = tid; r < NROW; r += 256) {
        s += g_rowloss[r];
        int f = g_flags[r];
        c += f & 1;
        k += (f >> 1) & 1;
    }
    ss[tid] = s; sc[tid] = c; sk[tid] = k;
    __syncthreads();
    for (int o = 128; o > 0; o >>= 1) {
        if (tid < o) { ss[tid] += ss[tid + o]; sc[tid] += sc[tid + o]; sk[tid] += sk[tid + o]; }
        __syncthreads();
    }
    if (tid == 0) {
        int cnt = sc[0]; if (cnt < 1) cnt = 1;
        out[0] = ss[0] / (float)cnt;
        out[1] = (float)sk[0];
    }
}

}  // namespace

extern "C" void kernel_launch(void* const* d_in, const int* in_sizes, int n_in,
                              void* d_out, int out_size) {
    const float* X       = (const float*)d_in[0];
    const float* pred    = (const float*)d_in[1];
    const int*   targets = (const int*)d_in[2];
    // d_in[3] = true_targets (unused by reference)
    const float* prob    = (const float*)d_in[4];
    const float* thr     = (const float*)d_in[5];
    float* out = (float*)d_out;

    cudaFuncSetAttribute(k_gemm, cudaFuncAttributeMaxDynamicSharedMemorySize,
                         SMEM_DYN);

    // JAX partitionable split: child key i = threefry2x32((0,42), (0, i))
    uint2 kp  = tf2x32(0u, 42u, 0u, 0u);
    uint2 kp2 = tf2x32(0u, 42u, 0u, 1u);

    k_prep<<<NROW / 8, 256>>>(X);
    dim3 g(NROW / 128, NROW / 128);
    k_gemm<<<g, 256, SMEM_DYN>>>();
    k_row<<<NROW, 256>>>(pred, targets, prob, thr, kp.x, kp.y, kp2.x, kp2.y);
    k_final<<<1, 256>>>(out);
}